// round 13
// baseline (speedup 1.0000x reference)
#include <cuda_runtime.h>

#define EDIM    4096
#define BATCH   8
#define HEADS   32
#define DHEAD   128
#define TPREV   2047
#define TTOT    2048
#define TOK_PER_WARP 256   // 8 warps x 256 tokens = 2048

#define GEMV_THREADS 512
#define GEMV_SMEM (BATCH * EDIM * sizeof(float))   // 128 KB dynamic smem

// ---------------- scratch (device globals, no allocation) ----------------
__device__ float g_q[BATCH * EDIM];   // only rows 3968..4095 (head 31) valid
__device__ float g_k[BATCH * EDIM];
__device__ float g_v[BATCH * EDIM];
__device__ float g_attn[BATCH * EDIM];

// ---------------- GEMV mainloop: 32 rows, 16 warps, K-split, prefetch-2 ---
// Computes Y[b][row] = sum_i xs[b][i]*W[row][i] + bias[row] for 32 rows
// starting at row0_blk. xs must already hold X in shared memory.
// Warps 0-7: K[0:2048]; warps 8-15: same rows, K[2048:4096].
__device__ __forceinline__ void gemv_mainloop(const float* __restrict__ xs,
                                              const float* __restrict__ W,
                                              const float* __restrict__ bias,
                                              float* __restrict__ Y,
                                              int row0_blk) {
    __shared__ float buf[2][32][8];                // cross-half partials

    const int warp  = threadIdx.x >> 5;
    const int lane  = threadIdx.x & 31;
    const int wrow4 = warp & 7;                    // row group 0..7
    const int half  = warp >> 3;                   // K half 0..1
    const int row0  = row0_blk + wrow4 * 4;
    const int kbase = half * 2048;

    float acc[4][8];
#pragma unroll
    for (int r = 0; r < 4; ++r)
#pragma unroll
        for (int b = 0; b < 8; ++b) acc[r][b] = 0.f;

    const float* w0 = W + (size_t)row0 * EDIM + kbase + lane * 4;

    // prologue: prefetch macro-steps 0 and 1
    float4 wA[4], wB[4];
#pragma unroll
    for (int r = 0; r < 4; ++r) wA[r] = *(const float4*)&w0[(size_t)r * EDIM];
#pragma unroll
    for (int r = 0; r < 4; ++r) wB[r] = *(const float4*)&w0[(size_t)r * EDIM + 128];

    // 16 macro-steps x 128 floats; prefetch ms+2 before computing ms
#pragma unroll
    for (int ms = 0; ms < 16; ++ms) {
        float4 wC[4];
        if (ms < 14) {
#pragma unroll
            for (int r = 0; r < 4; ++r)
                wC[r] = *(const float4*)&w0[(size_t)r * EDIM + (ms + 2) * 128];
        }
        const int i = kbase + ms * 128 + lane * 4;
#pragma unroll
        for (int b = 0; b < 8; ++b) {
            const float4 x4 = *(const float4*)&xs[b * EDIM + i];
#pragma unroll
            for (int r = 0; r < 4; ++r) {
                acc[r][b] += wA[r].x * x4.x + wA[r].y * x4.y
                           + wA[r].z * x4.z + wA[r].w * x4.w;
            }
        }
#pragma unroll
        for (int r = 0; r < 4; ++r) { wA[r] = wB[r]; wB[r] = wC[r]; }
    }

    // warp-reduce 32 accumulators; lane = r*8+b holds its value
#pragma unroll
    for (int r = 0; r < 4; ++r)
#pragma unroll
        for (int b = 0; b < 8; ++b) {
            float v = acc[r][b];
#pragma unroll
            for (int s = 16; s > 0; s >>= 1)
                v += __shfl_xor_sync(0xffffffffu, v, s);
            acc[r][b] = v;
        }
    {
        const int r = lane >> 3;
        const int b = lane & 7;
        buf[half][wrow4 * 4 + r][b] = acc[r][b];
    }
    __syncthreads();

    // merge the two K halves: 256 threads cover 32 rows x 8 batches
    if (threadIdx.x < 256) {
        const int rl = threadIdx.x >> 3;
        const int b  = threadIdx.x & 7;
        const int row = row0_blk + rl;
        Y[b * EDIM + row] = buf[0][rl][b] + buf[1][rl][b] + bias[row];
    }
}

// ---------------- projections: K(128) + V(128) + Q-slice(4) in ONE launch --
__global__ __launch_bounds__(GEMV_THREADS)
void proj_gemv(const float* __restrict__ x,
               const float* __restrict__ Wk, const float* __restrict__ bk,
               const float* __restrict__ Wv, const float* __restrict__ bv,
               const float* __restrict__ Wq, const float* __restrict__ bq) {
    extern __shared__ float xs[];   // [BATCH * EDIM]

    // stage all of x: 8192 float4 over 512 threads
#pragma unroll
    for (int t = threadIdx.x; t < 8192; t += GEMV_THREADS) {
        const int b = t >> 10;
        const int i = (t & 1023) * 4;
        *(float4*)&xs[b * EDIM + i] = *(const float4*)&x[b * EDIM + i];
    }
    __syncthreads();

    const int id = blockIdx.x;
    if (id < 128)
        gemv_mainloop(xs, Wk, bk, g_k, id * 32);
    else if (id < 256)
        gemv_mainloop(xs, Wv, bv, g_v, (id - 128) * 32);
    else  // 4 blocks: q rows 3968..4095 (head 31 only — all the reference uses)
        gemv_mainloop(xs, Wq, bq, g_q, (HEADS - 1) * DHEAD + (id - 256) * 32);
}

// ---------------- output projection (stages g_attn, then GEMV) ------------
__global__ __launch_bounds__(GEMV_THREADS)
void out_gemv(const float* __restrict__ Wo,
              const float* __restrict__ bo,
              float* __restrict__ out) {
    extern __shared__ float xs[];   // [BATCH * EDIM]
#pragma unroll
    for (int t = threadIdx.x; t < 8192; t += GEMV_THREADS) {
        const int b = t >> 10;
        const int i = (t & 1023) * 4;
        *(float4*)&xs[b * EDIM + i] = *(const float4*)&g_attn[b * EDIM + i];
    }
    __syncthreads();
    gemv_mainloop(xs, Wo, bo, out, blockIdx.x * 32);
}

// ---------------- fused cache-copy + flash attention (no split-K) ---------
// grid: (HEADS, BATCH) = 256 blocks, 256 threads (8 warps x 256 tokens).
// One block handles the full 2048-token sequence for its (b,h); the
// cross-warp softmax combine happens once in smem; result -> g_attn.
// NOTE: the reference slices q AFTER transposing to (b, h, s, d), so
// q[:, -1:] selects the LAST HEAD (h=31), broadcast to all heads.
__global__ void attn_kernel(const float* __restrict__ kc,
                            const float* __restrict__ vc,
                            float* __restrict__ kout,
                            float* __restrict__ vout) {
    const int h = blockIdx.x;
    const int b = blockIdx.y;
    const int warp = threadIdx.x >> 5;
    const int lane = threadIdx.x & 31;
    const int bh = b * HEADS + h;

    // q from head 31 for ALL heads (reference broadcast semantics)
    const float4 q4 = *(const float4*)&g_q[b * EDIM + (HEADS - 1) * DHEAD + lane * 4];
    const float scale = 0.08838834764831845f;  // 1/sqrt(128)

    float m = -1e30f, l = 0.f;
    float4 acc = make_float4(0.f, 0.f, 0.f, 0.f);

    const int tok0 = warp * TOK_PER_WARP;

#pragma unroll 4
    for (int j = 0; j < TOK_PER_WARP; ++j) {
        const int tok = tok0 + j;
        const float* kp;
        const float* vp;
        if (tok < TPREV) {
            const size_t off = ((size_t)bh * TPREV + tok) * DHEAD;
            kp = kc + off;
            vp = vc + off;
        } else {
            kp = g_k + b * EDIM + h * DHEAD;
            vp = g_v + b * EDIM + h * DHEAD;
        }
        const float4 k4 = *(const float4*)&kp[lane * 4];
        const float4 v4 = *(const float4*)&vp[lane * 4];

        // cache copy rides the same read
        const size_t oo = ((size_t)bh * TTOT + tok) * DHEAD + lane * 4;
        *(float4*)&kout[oo] = k4;
        *(float4*)&vout[oo] = v4;

        float s = q4.x * k4.x + q4.y * k4.y + q4.z * k4.z + q4.w * k4.w;
#pragma unroll
        for (int sh = 16; sh > 0; sh >>= 1)
            s += __shfl_xor_sync(0xffffffffu, s, sh);
        s *= scale;

        const float mn = fmaxf(m, s);
        const float sc = __expf(m - mn);
        const float p  = __expf(s - mn);
        l = l * sc + p;
        acc.x = acc.x * sc + p * v4.x;
        acc.y = acc.y * sc + p * v4.y;
        acc.z = acc.z * sc + p * v4.z;
        acc.w = acc.w * sc + p * v4.w;
        m = mn;
    }

    // combine the 8 warps of this block and write g_attn directly
    __shared__ float sm_m[8], sm_l[8];
    __shared__ __align__(16) float sm_acc[8][DHEAD];
    if (lane == 0) { sm_m[warp] = m; sm_l[warp] = l; }
    *(float4*)&sm_acc[warp][lane * 4] = acc;
    __syncthreads();

    if (threadIdx.x < DHEAD) {
        const int d = threadIdx.x;
        float M = -1e30f;
#pragma unroll
        for (int w = 0; w < 8; ++w) M = fmaxf(M, sm_m[w]);
        float L = 0.f, A = 0.f;
#pragma unroll
        for (int w = 0; w < 8; ++w) {
            const float e = __expf(sm_m[w] - M);
            L += sm_l[w] * e;
            A += sm_acc[w][d] * e;
        }
        g_attn[b * EDIM + h * DHEAD + d] = A / L;
    }
}

// ---------------- launch ---------------------------------------------------
extern "C" void kernel_launch(void* const* d_in, const int* in_sizes, int n_in,
                              void* d_out, int out_size) {
    // Defensive input mapping based on element counts.
    const float *x, *kc, *vc, *Wq, *bq, *Wk, *bk, *Wv, *bv, *Wo, *bo;
    if (in_sizes[0] == BATCH * EDIM) {
        // signature/dict order: x, kc, vc, Wq, bq, Wk, bk, Wv, bv, Wo, bo
        x  = (const float*)d_in[0];
        kc = (const float*)d_in[1];
        vc = (const float*)d_in[2];
        Wq = (const float*)d_in[3];
        bq = (const float*)d_in[4];
        Wk = (const float*)d_in[5];
        bk = (const float*)d_in[6];
        Wv = (const float*)d_in[7];
        bv = (const float*)d_in[8];
        Wo = (const float*)d_in[9];
        bo = (const float*)d_in[10];
    } else {
        // alphabetical order: Wk, Wo, Wq, Wv, bk, bo, bq, bv, kc, vc, x
        Wk = (const float*)d_in[0];
        Wo = (const float*)d_in[1];
        Wq = (const float*)d_in[2];
        Wv = (const float*)d_in[3];
        bk = (const float*)d_in[4];
        bo = (const float*)d_in[5];
        bq = (const float*)d_in[6];
        bv = (const float*)d_in[7];
        kc = (const float*)d_in[8];
        vc = (const float*)d_in[9];
        x  = (const float*)d_in[10];
    }

    float* out  = (float*)d_out;                                   // [8,1,4096]
    float* kout = out + (size_t)BATCH * EDIM;                      // [8,32,2048,128]
    float* vout = kout + (size_t)BATCH * HEADS * TTOT * DHEAD;     // [8,32,2048,128]

    // allow 128KB dynamic smem (idempotent; capture-safe)
    static int smem_set = 0;
    if (!smem_set) {
        cudaFuncSetAttribute(proj_gemv, cudaFuncAttributeMaxDynamicSharedMemorySize,
                             (int)GEMV_SMEM);
        cudaFuncSetAttribute(out_gemv, cudaFuncAttributeMaxDynamicSharedMemorySize,
                             (int)GEMV_SMEM);
        smem_set = 1;
    }

    proj_gemv<<<260, GEMV_THREADS, GEMV_SMEM>>>(x, Wk, bk, Wv, bv, Wq, bq);
    attn_kernel<<<dim3(HEADS, BATCH), 256>>>(kc, vc, kout, vout);
    out_gemv<<<128, GEMV_THREADS, GEMV_SMEM>>>(Wo, bo, out);
}

// round 14
// speedup vs baseline: 1.4267x; 1.4267x over previous
#include <cuda_runtime.h>

#define EDIM    4096
#define BATCH   8
#define HEADS   32
#define DHEAD   128
#define TPREV   2047
#define TTOT    2048
#define NSPLIT  8
#define TOK_PER_BLOCK 256   // 8 warps * 32 tokens

#define GEMV_THREADS 512
#define GEMV_SMEM (BATCH * EDIM * sizeof(float))   // 128 KB dynamic smem

// ---------------- scratch (device globals, no allocation) ----------------
__device__ float g_q[BATCH * EDIM];   // only rows 3968..4095 (head 31) valid
__device__ float g_k[BATCH * EDIM];
__device__ float g_v[BATCH * EDIM];
__device__ float g_attn[BATCH * EDIM];
__device__ float g_pm[BATCH * HEADS * NSPLIT];
__device__ float g_pl[BATCH * HEADS * NSPLIT];
__device__ float g_pacc[BATCH * HEADS * NSPLIT * DHEAD];

// ---------------- packed f32x2 FMA helpers --------------------------------
__device__ __forceinline__ void ffma2(unsigned long long& d,
                                      unsigned long long a,
                                      unsigned long long b) {
    asm("fma.rn.f32x2 %0, %1, %2, %0;" : "+l"(d) : "l"(a), "l"(b));
}
__device__ __forceinline__ float unpack_sum(unsigned long long v) {
    float lo, hi;
    asm("mov.b64 {%0, %1}, %2;" : "=f"(lo), "=f"(hi) : "l"(v));
    return lo + hi;
}

// ---------------- GEMV mainloop: 32 rows, 16 warps, K-split, f32x2 --------
// Computes Y[b][row] = sum_i xs[b][i]*W[row][i] + bias[row] for 32 rows
// starting at row0_blk. xs must already hold X in shared memory.
// Warps 0-7: K[0:2048]; warps 8-15: same rows, K[2048:4096].
// FMA uses packed f32x2 (half the FFMA instructions); x-smem loads run
// one batch ahead; W loads run ~1 macro-step ahead.
__device__ __forceinline__ void gemv_mainloop(const float* __restrict__ xs,
                                              const float* __restrict__ W,
                                              const float* __restrict__ bias,
                                              float* __restrict__ Y,
                                              int row0_blk) {
    __shared__ float buf[2][32][8];                // cross-half partials

    const int warp  = threadIdx.x >> 5;
    const int lane  = threadIdx.x & 31;
    const int wrow4 = warp & 7;                    // row group 0..7
    const int half  = warp >> 3;                   // K half 0..1
    const int row0  = row0_blk + wrow4 * 4;
    const int kbase = half * 2048;

    unsigned long long acc2[4][8];
#pragma unroll
    for (int r = 0; r < 4; ++r)
#pragma unroll
        for (int b = 0; b < 8; ++b) acc2[r][b] = 0ull;

    const float* w0 = W + (size_t)row0 * EDIM + kbase + lane * 4;

    // double-buffered W prefetch (wA = current, wB = next)
    ulonglong2 wA[4], wB[4];
#pragma unroll
    for (int r = 0; r < 4; ++r)
        wA[r] = *(const ulonglong2*)&w0[(size_t)r * EDIM];
#pragma unroll
    for (int r = 0; r < 4; ++r)
        wB[r] = *(const ulonglong2*)&w0[(size_t)r * EDIM + 128];

    // 16 macro-steps x 128 floats
#pragma unroll
    for (int ms = 0; ms < 16; ++ms) {
        const int i = kbase + ms * 128 + lane * 4;
        // x pipeline: load batch b+1 while computing batch b
        ulonglong2 xc = *(const ulonglong2*)&xs[i];
#pragma unroll
        for (int b = 0; b < 8; ++b) {
            ulonglong2 xn;
            if (b < 7) xn = *(const ulonglong2*)&xs[(b + 1) * EDIM + i];
#pragma unroll
            for (int r = 0; r < 4; ++r) {
                ffma2(acc2[r][b], wA[r].x, xc.x);
                ffma2(acc2[r][b], wA[r].y, xc.y);
            }
            xc = xn;
        }
        // shift and prefetch next-next W
#pragma unroll
        for (int r = 0; r < 4; ++r) wA[r] = wB[r];
        if (ms < 14) {
#pragma unroll
            for (int r = 0; r < 4; ++r)
                wB[r] = *(const ulonglong2*)&w0[(size_t)r * EDIM + (ms + 2) * 128];
        }
    }

    // unpack + warp-reduce 32 accumulators; lane = r*8+b holds its value
    float accs[4][8];
#pragma unroll
    for (int r = 0; r < 4; ++r)
#pragma unroll
        for (int b = 0; b < 8; ++b) {
            float v = unpack_sum(acc2[r][b]);
#pragma unroll
            for (int s = 16; s > 0; s >>= 1)
                v += __shfl_xor_sync(0xffffffffu, v, s);
            accs[r][b] = v;
        }
    {
        const int r = lane >> 3;
        const int b = lane & 7;
        buf[half][wrow4 * 4 + r][b] = accs[r][b];
    }
    __syncthreads();

    // merge the two K halves: 256 threads cover 32 rows x 8 batches
    if (threadIdx.x < 256) {
        const int rl = threadIdx.x >> 3;
        const int b  = threadIdx.x & 7;
        const int row = row0_blk + rl;
        Y[b * EDIM + row] = buf[0][rl][b] + buf[1][rl][b] + bias[row];
    }
}

// ---------------- projections: K(128) + V(128) + Q-slice(4) in ONE launch --
__global__ __launch_bounds__(GEMV_THREADS)
void proj_gemv(const float* __restrict__ x,
               const float* __restrict__ Wk, const float* __restrict__ bk,
               const float* __restrict__ Wv, const float* __restrict__ bv,
               const float* __restrict__ Wq, const float* __restrict__ bq) {
    extern __shared__ float xs[];   // [BATCH * EDIM]

    // stage all of x: 8192 float4 over 512 threads
#pragma unroll
    for (int t = threadIdx.x; t < 8192; t += GEMV_THREADS) {
        const int b = t >> 10;
        const int i = (t & 1023) * 4;
        *(float4*)&xs[b * EDIM + i] = *(const float4*)&x[b * EDIM + i];
    }
    __syncthreads();

    const int id = blockIdx.x;
    if (id < 128)
        gemv_mainloop(xs, Wk, bk, g_k, id * 32);
    else if (id < 256)
        gemv_mainloop(xs, Wv, bv, g_v, (id - 128) * 32);
    else  // 4 blocks: q rows 3968..4095 (head 31 only — all the reference uses)
        gemv_mainloop(xs, Wq, bq, g_q, (HEADS - 1) * DHEAD + (id - 256) * 32);
}

// ---------------- output projection (stages g_attn, then GEMV) ------------
__global__ __launch_bounds__(GEMV_THREADS)
void out_gemv(const float* __restrict__ Wo,
              const float* __restrict__ bo,
              float* __restrict__ out) {
    extern __shared__ float xs[];   // [BATCH * EDIM]
#pragma unroll
    for (int t = threadIdx.x; t < 8192; t += GEMV_THREADS) {
        const int b = t >> 10;
        const int i = (t & 1023) * 4;
        *(float4*)&xs[b * EDIM + i] = *(const float4*)&g_attn[b * EDIM + i];
    }
    __syncthreads();
    gemv_mainloop(xs, Wo, bo, out, blockIdx.x * 32);
}

// ---------------- fused cache-copy + flash attention (split-8, R11) -------
// grid: (NSPLIT, HEADS, BATCH), block 256 (8 warps x 32 tokens each)
// NOTE: the reference slices q AFTER transposing to (b, h, s, d), so
// q[:, -1:] selects the LAST HEAD (h=31), broadcast to all heads.
__global__ void attn_kernel(const float* __restrict__ kc,
                            const float* __restrict__ vc,
                            float* __restrict__ kout,
                            float* __restrict__ vout) {
    const int split = blockIdx.x;
    const int h = blockIdx.y;
    const int b = blockIdx.z;
    const int warp = threadIdx.x >> 5;
    const int lane = threadIdx.x & 31;
    const int bh = b * HEADS + h;

    // q from head 31 for ALL heads (reference broadcast semantics)
    const float4 q4 = *(const float4*)&g_q[b * EDIM + (HEADS - 1) * DHEAD + lane * 4];
    const float scale = 0.08838834764831845f;  // 1/sqrt(128)

    float m = -1e30f, l = 0.f;
    float4 acc = make_float4(0.f, 0.f, 0.f, 0.f);

    const int tok0 = split * TOK_PER_BLOCK + warp * 32;

#pragma unroll 4
    for (int j = 0; j < 32; ++j) {
        const int tok = tok0 + j;
        const float* kp;
        const float* vp;
        if (tok < TPREV) {
            const size_t off = ((size_t)bh * TPREV + tok) * DHEAD;
            kp = kc + off;
            vp = vc + off;
        } else {
            kp = g_k + b * EDIM + h * DHEAD;
            vp = g_v + b * EDIM + h * DHEAD;
        }
        const float4 k4 = *(const float4*)&kp[lane * 4];
        const float4 v4 = *(const float4*)&vp[lane * 4];

        // cache copy rides the same read
        const size_t oo = ((size_t)bh * TTOT + tok) * DHEAD + lane * 4;
        *(float4*)&kout[oo] = k4;
        *(float4*)&vout[oo] = v4;

        float s = q4.x * k4.x + q4.y * k4.y + q4.z * k4.z + q4.w * k4.w;
#pragma unroll
        for (int sh = 16; sh > 0; sh >>= 1)
            s += __shfl_xor_sync(0xffffffffu, s, sh);
        s *= scale;

        const float mn = fmaxf(m, s);
        const float sc = __expf(m - mn);
        const float p  = __expf(s - mn);
        l = l * sc + p;
        acc.x = acc.x * sc + p * v4.x;
        acc.y = acc.y * sc + p * v4.y;
        acc.z = acc.z * sc + p * v4.z;
        acc.w = acc.w * sc + p * v4.w;
        m = mn;
    }

    // combine the 8 warps of this block
    __shared__ float sm_m[8], sm_l[8];
    __shared__ __align__(16) float sm_acc[8][DHEAD];
    if (lane == 0) { sm_m[warp] = m; sm_l[warp] = l; }
    *(float4*)&sm_acc[warp][lane * 4] = acc;
    __syncthreads();

    if (threadIdx.x < DHEAD) {
        const int d = threadIdx.x;
        float M = -1e30f;
#pragma unroll
        for (int w = 0; w < 8; ++w) M = fmaxf(M, sm_m[w]);
        float L = 0.f, A = 0.f;
#pragma unroll
        for (int w = 0; w < 8; ++w) {
            const float e = __expf(sm_m[w] - M);
            L += sm_l[w] * e;
            A += sm_acc[w][d] * e;
        }
        const int idx = bh * NSPLIT + split;
        g_pacc[idx * DHEAD + d] = A;
        if (d == 0) { g_pm[idx] = M; g_pl[idx] = L; }
    }
}

// merge NSPLIT partial softmaxes per (b,h)
__global__ void combine_kernel() {
    const int bh = blockIdx.x;   // 0..255
    const int d = threadIdx.x;   // 0..127
    float M = -1e30f;
#pragma unroll
    for (int s = 0; s < NSPLIT; ++s)
        M = fmaxf(M, g_pm[bh * NSPLIT + s]);
    float L = 0.f, A = 0.f;
#pragma unroll
    for (int s = 0; s < NSPLIT; ++s) {
        const float e = __expf(g_pm[bh * NSPLIT + s] - M);
        L += g_pl[bh * NSPLIT + s] * e;
        A += g_pacc[(bh * NSPLIT + s) * DHEAD + d] * e;
    }
    const int b = bh / HEADS;
    const int h = bh % HEADS;
    g_attn[b * EDIM + h * DHEAD + d] = A / L;
}

// ---------------- launch ---------------------------------------------------
extern "C" void kernel_launch(void* const* d_in, const int* in_sizes, int n_in,
                              void* d_out, int out_size) {
    // Defensive input mapping based on element counts.
    const float *x, *kc, *vc, *Wq, *bq, *Wk, *bk, *Wv, *bv, *Wo, *bo;
    if (in_sizes[0] == BATCH * EDIM) {
        // signature/dict order: x, kc, vc, Wq, bq, Wk, bk, Wv, bv, Wo, bo
        x  = (const float*)d_in[0];
        kc = (const float*)d_in[1];
        vc = (const float*)d_in[2];
        Wq = (const float*)d_in[3];
        bq = (const float*)d_in[4];
        Wk = (const float*)d_in[5];
        bk = (const float*)d_in[6];
        Wv = (const float*)d_in[7];
        bv = (const float*)d_in[8];
        Wo = (const float*)d_in[9];
        bo = (const float*)d_in[10];
    } else {
        // alphabetical order: Wk, Wo, Wq, Wv, bk, bo, bq, bv, kc, vc, x
        Wk = (const float*)d_in[0];
        Wo = (const float*)d_in[1];
        Wq = (const float*)d_in[2];
        Wv = (const float*)d_in[3];
        bk = (const float*)d_in[4];
        bo = (const float*)d_in[5];
        bq = (const float*)d_in[6];
        bv = (const float*)d_in[7];
        kc = (const float*)d_in[8];
        vc = (const float*)d_in[9];
        x  = (const float*)d_in[10];
    }

    float* out  = (float*)d_out;                                   // [8,1,4096]
    float* kout = out + (size_t)BATCH * EDIM;                      // [8,32,2048,128]
    float* vout = kout + (size_t)BATCH * HEADS * TTOT * DHEAD;     // [8,32,2048,128]

    // allow 128KB dynamic smem (idempotent; capture-safe)
    static int smem_set = 0;
    if (!smem_set) {
        cudaFuncSetAttribute(proj_gemv, cudaFuncAttributeMaxDynamicSharedMemorySize,
                             (int)GEMV_SMEM);
        cudaFuncSetAttribute(out_gemv, cudaFuncAttributeMaxDynamicSharedMemorySize,
                             (int)GEMV_SMEM);
        smem_set = 1;
    }

    proj_gemv<<<260, GEMV_THREADS, GEMV_SMEM>>>(x, Wk, bk, Wv, bv, Wq, bq);
    attn_kernel<<<dim3(NSPLIT, HEADS, BATCH), 256>>>(kc, vc, kout, vout);
    combine_kernel<<<BATCH * HEADS, DHEAD>>>();
    out_gemv<<<128, GEMV_THREADS, GEMV_SMEM>>>(Wo, bo, out);
}

// round 15
// speedup vs baseline: 1.4446x; 1.0126x over previous
#include <cuda_runtime.h>

#define EDIM    4096
#define BATCH   8
#define HEADS   32
#define DHEAD   128
#define TPREV   2047
#define TTOT    2048
#define NSPLIT  8
#define TOK_PER_BLOCK 256   // 8 warps * 32 tokens

#define GEMV_THREADS 512
#define GEMV_SMEM (BATCH * EDIM * sizeof(float))   // 128 KB dynamic smem

// ---------------- scratch (device globals, no allocation) ----------------
__device__ float g_q[BATCH * EDIM];   // only rows 3968..4095 (head 31) valid
__device__ float g_k[BATCH * EDIM];
__device__ float g_v[BATCH * EDIM];
__device__ float g_attn[BATCH * EDIM];
__device__ float g_pm[BATCH * HEADS * NSPLIT];
__device__ float g_pl[BATCH * HEADS * NSPLIT];
__device__ float g_pacc[BATCH * HEADS * NSPLIT * DHEAD];
__device__ unsigned int g_cnt[BATCH * HEADS];   // split-arrival counters

// ---------------- packed f32x2 FMA helpers --------------------------------
__device__ __forceinline__ void ffma2(unsigned long long& d,
                                      unsigned long long a,
                                      unsigned long long b) {
    asm("fma.rn.f32x2 %0, %1, %2, %0;" : "+l"(d) : "l"(a), "l"(b));
}
__device__ __forceinline__ float unpack_sum(unsigned long long v) {
    float lo, hi;
    asm("mov.b64 {%0, %1}, %2;" : "=f"(lo), "=f"(hi) : "l"(v));
    return lo + hi;
}

// ---------------- GEMV mainloop: 32 rows, 16 warps, K-split, f32x2 --------
// Computes Y[b][row] = sum_i xs[b][i]*W[row][i] + bias[row] for 32 rows
// starting at row0_blk. xs must already hold X in shared memory.
// Warps 0-7: K[0:2048]; warps 8-15: same rows, K[2048:4096].
// Packed f32x2 FMA; W loads prefetched 2 macro-steps ahead.
__device__ __forceinline__ void gemv_mainloop(const float* __restrict__ xs,
                                              const float* __restrict__ W,
                                              const float* __restrict__ bias,
                                              float* __restrict__ Y,
                                              int row0_blk) {
    __shared__ float buf[2][32][8];                // cross-half partials

    const int warp  = threadIdx.x >> 5;
    const int lane  = threadIdx.x & 31;
    const int wrow4 = warp & 7;                    // row group 0..7
    const int half  = warp >> 3;                   // K half 0..1
    const int row0  = row0_blk + wrow4 * 4;
    const int kbase = half * 2048;

    unsigned long long acc2[4][8];
#pragma unroll
    for (int r = 0; r < 4; ++r)
#pragma unroll
        for (int b = 0; b < 8; ++b) acc2[r][b] = 0ull;

    const float* w0 = W + (size_t)row0 * EDIM + kbase + lane * 4;

    // double-buffered W prefetch (wA = current, wB = next)
    ulonglong2 wA[4], wB[4];
#pragma unroll
    for (int r = 0; r < 4; ++r)
        wA[r] = *(const ulonglong2*)&w0[(size_t)r * EDIM];
#pragma unroll
    for (int r = 0; r < 4; ++r)
        wB[r] = *(const ulonglong2*)&w0[(size_t)r * EDIM + 128];

    // 16 macro-steps x 128 floats; prefetch ms+2 FIRST, then compute ms
#pragma unroll
    for (int ms = 0; ms < 16; ++ms) {
        ulonglong2 wC[4];
        if (ms < 14) {
#pragma unroll
            for (int r = 0; r < 4; ++r)
                wC[r] = *(const ulonglong2*)&w0[(size_t)r * EDIM + (ms + 2) * 128];
        }
        const int i = kbase + ms * 128 + lane * 4;
#pragma unroll
        for (int b = 0; b < 8; ++b) {
            const ulonglong2 xc = *(const ulonglong2*)&xs[b * EDIM + i];
#pragma unroll
            for (int r = 0; r < 4; ++r) {
                ffma2(acc2[r][b], wA[r].x, xc.x);
                ffma2(acc2[r][b], wA[r].y, xc.y);
            }
        }
#pragma unroll
        for (int r = 0; r < 4; ++r) { wA[r] = wB[r]; wB[r] = wC[r]; }
    }

    // unpack + warp-reduce 32 accumulators; lane = r*8+b holds its value
    float accs[4][8];
#pragma unroll
    for (int r = 0; r < 4; ++r)
#pragma unroll
        for (int b = 0; b < 8; ++b) {
            float v = unpack_sum(acc2[r][b]);
#pragma unroll
            for (int s = 16; s > 0; s >>= 1)
                v += __shfl_xor_sync(0xffffffffu, v, s);
            accs[r][b] = v;
        }
    {
        const int r = lane >> 3;
        const int b = lane & 7;
        buf[half][wrow4 * 4 + r][b] = accs[r][b];
    }
    __syncthreads();

    // merge the two K halves: 256 threads cover 32 rows x 8 batches
    if (threadIdx.x < 256) {
        const int rl = threadIdx.x >> 3;
        const int b  = threadIdx.x & 7;
        const int row = row0_blk + rl;
        Y[b * EDIM + row] = buf[0][rl][b] + buf[1][rl][b] + bias[row];
    }
}

// ---------------- projections: K(128) + V(128) + Q-slice(4) in ONE launch --
__global__ __launch_bounds__(GEMV_THREADS)
void proj_gemv(const float* __restrict__ x,
               const float* __restrict__ Wk, const float* __restrict__ bk,
               const float* __restrict__ Wv, const float* __restrict__ bv,
               const float* __restrict__ Wq, const float* __restrict__ bq) {
    extern __shared__ float xs[];   // [BATCH * EDIM]

    // block 259 also zeroes the attn split counters (runs before attn_kernel)
    if (blockIdx.x == 259 && threadIdx.x < BATCH * HEADS)
        g_cnt[threadIdx.x] = 0u;

    // stage all of x: 8192 float4 over 512 threads
#pragma unroll
    for (int t = threadIdx.x; t < 8192; t += GEMV_THREADS) {
        const int b = t >> 10;
        const int i = (t & 1023) * 4;
        *(float4*)&xs[b * EDIM + i] = *(const float4*)&x[b * EDIM + i];
    }
    __syncthreads();

    const int id = blockIdx.x;
    if (id < 128)
        gemv_mainloop(xs, Wk, bk, g_k, id * 32);
    else if (id < 256)
        gemv_mainloop(xs, Wv, bv, g_v, (id - 128) * 32);
    else  // 4 blocks: q rows 3968..4095 (head 31 only — all the reference uses)
        gemv_mainloop(xs, Wq, bq, g_q, (HEADS - 1) * DHEAD + (id - 256) * 32);
}

// ---------------- output projection (stages g_attn, then GEMV) ------------
__global__ __launch_bounds__(GEMV_THREADS)
void out_gemv(const float* __restrict__ Wo,
              const float* __restrict__ bo,
              float* __restrict__ out) {
    extern __shared__ float xs[];   // [BATCH * EDIM]
#pragma unroll
    for (int t = threadIdx.x; t < 8192; t += GEMV_THREADS) {
        const int b = t >> 10;
        const int i = (t & 1023) * 4;
        *(float4*)&xs[b * EDIM + i] = *(const float4*)&g_attn[b * EDIM + i];
    }
    __syncthreads();
    gemv_mainloop(xs, Wo, bo, out, blockIdx.x * 32);
}

// ---------------- fused cache-copy + flash attention + inline combine -----
// grid: (NSPLIT, HEADS, BATCH), block 256 (8 warps x 32 tokens each).
// The LAST block to finish for each (b,h) merges the 8 split partials and
// writes g_attn (combine_kernel folded in; deterministic — same 8 inputs,
// same order, whoever runs it).
// NOTE: the reference slices q AFTER transposing to (b, h, s, d), so
// q[:, -1:] selects the LAST HEAD (h=31), broadcast to all heads.
__global__ void attn_kernel(const float* __restrict__ kc,
                            const float* __restrict__ vc,
                            float* __restrict__ kout,
                            float* __restrict__ vout) {
    const int split = blockIdx.x;
    const int h = blockIdx.y;
    const int b = blockIdx.z;
    const int warp = threadIdx.x >> 5;
    const int lane = threadIdx.x & 31;
    const int bh = b * HEADS + h;

    // q from head 31 for ALL heads (reference broadcast semantics)
    const float4 q4 = *(const float4*)&g_q[b * EDIM + (HEADS - 1) * DHEAD + lane * 4];
    const float scale = 0.08838834764831845f;  // 1/sqrt(128)

    float m = -1e30f, l = 0.f;
    float4 acc = make_float4(0.f, 0.f, 0.f, 0.f);

    const int tok0 = split * TOK_PER_BLOCK + warp * 32;

#pragma unroll 4
    for (int j = 0; j < 32; ++j) {
        const int tok = tok0 + j;
        const float* kp;
        const float* vp;
        if (tok < TPREV) {
            const size_t off = ((size_t)bh * TPREV + tok) * DHEAD;
            kp = kc + off;
            vp = vc + off;
        } else {
            kp = g_k + b * EDIM + h * DHEAD;
            vp = g_v + b * EDIM + h * DHEAD;
        }
        const float4 k4 = *(const float4*)&kp[lane * 4];
        const float4 v4 = *(const float4*)&vp[lane * 4];

        // cache copy rides the same read
        const size_t oo = ((size_t)bh * TTOT + tok) * DHEAD + lane * 4;
        *(float4*)&kout[oo] = k4;
        *(float4*)&vout[oo] = v4;

        float s = q4.x * k4.x + q4.y * k4.y + q4.z * k4.z + q4.w * k4.w;
#pragma unroll
        for (int sh = 16; sh > 0; sh >>= 1)
            s += __shfl_xor_sync(0xffffffffu, s, sh);
        s *= scale;

        const float mn = fmaxf(m, s);
        const float sc = __expf(m - mn);
        const float p  = __expf(s - mn);
        l = l * sc + p;
        acc.x = acc.x * sc + p * v4.x;
        acc.y = acc.y * sc + p * v4.y;
        acc.z = acc.z * sc + p * v4.z;
        acc.w = acc.w * sc + p * v4.w;
        m = mn;
    }

    // combine the 8 warps of this block
    __shared__ float sm_m[8], sm_l[8];
    __shared__ __align__(16) float sm_acc[8][DHEAD];
    __shared__ int s_last;
    if (lane == 0) { sm_m[warp] = m; sm_l[warp] = l; }
    *(float4*)&sm_acc[warp][lane * 4] = acc;
    __syncthreads();

    if (threadIdx.x < DHEAD) {
        const int d = threadIdx.x;
        float M = -1e30f;
#pragma unroll
        for (int w = 0; w < 8; ++w) M = fmaxf(M, sm_m[w]);
        float L = 0.f, A = 0.f;
#pragma unroll
        for (int w = 0; w < 8; ++w) {
            const float e = __expf(sm_m[w] - M);
            L += sm_l[w] * e;
            A += sm_acc[w][d] * e;
        }
        const int idx = bh * NSPLIT + split;
        g_pacc[idx * DHEAD + d] = A;
        if (d == 0) { g_pm[idx] = M; g_pl[idx] = L; }
    }
    __syncthreads();

    // last-arriving split block performs the cross-split combine
    if (threadIdx.x == 0) {
        __threadfence();
        s_last = (atomicAdd(&g_cnt[bh], 1u) == NSPLIT - 1);
    }
    __syncthreads();

    if (s_last && threadIdx.x < DHEAD) {
        __threadfence();   // acquire: see all 8 splits' partials
        const int d = threadIdx.x;
        float M = -1e30f;
#pragma unroll
        for (int s = 0; s < NSPLIT; ++s)
            M = fmaxf(M, g_pm[bh * NSPLIT + s]);
        float L = 0.f, A = 0.f;
#pragma unroll
        for (int s = 0; s < NSPLIT; ++s) {
            const float e = __expf(g_pm[bh * NSPLIT + s] - M);
            L += g_pl[bh * NSPLIT + s] * e;
            A += g_pacc[(bh * NSPLIT + s) * DHEAD + d] * e;
        }
        g_attn[b * EDIM + h * DHEAD + d] = A / L;
    }
}

// ---------------- launch ---------------------------------------------------
extern "C" void kernel_launch(void* const* d_in, const int* in_sizes, int n_in,
                              void* d_out, int out_size) {
    // Defensive input mapping based on element counts.
    const float *x, *kc, *vc, *Wq, *bq, *Wk, *bk, *Wv, *bv, *Wo, *bo;
    if (in_sizes[0] == BATCH * EDIM) {
        // signature/dict order: x, kc, vc, Wq, bq, Wk, bk, Wv, bv, Wo, bo
        x  = (const float*)d_in[0];
        kc = (const float*)d_in[1];
        vc = (const float*)d_in[2];
        Wq = (const float*)d_in[3];
        bq = (const float*)d_in[4];
        Wk = (const float*)d_in[5];
        bk = (const float*)d_in[6];
        Wv = (const float*)d_in[7];
        bv = (const float*)d_in[8];
        Wo = (const float*)d_in[9];
        bo = (const float*)d_in[10];
    } else {
        // alphabetical order: Wk, Wo, Wq, Wv, bk, bo, bq, bv, kc, vc, x
        Wk = (const float*)d_in[0];
        Wo = (const float*)d_in[1];
        Wq = (const float*)d_in[2];
        Wv = (const float*)d_in[3];
        bk = (const float*)d_in[4];
        bo = (const float*)d_in[5];
        bq = (const float*)d_in[6];
        bv = (const float*)d_in[7];
        kc = (const float*)d_in[8];
        vc = (const float*)d_in[9];
        x  = (const float*)d_in[10];
    }

    float* out  = (float*)d_out;                                   // [8,1,4096]
    float* kout = out + (size_t)BATCH * EDIM;                      // [8,32,2048,128]
    float* vout = kout + (size_t)BATCH * HEADS * TTOT * DHEAD;     // [8,32,2048,128]

    // allow 128KB dynamic smem (idempotent; capture-safe)
    static int smem_set = 0;
    if (!smem_set) {
        cudaFuncSetAttribute(proj_gemv, cudaFuncAttributeMaxDynamicSharedMemorySize,
                             (int)GEMV_SMEM);
        cudaFuncSetAttribute(out_gemv, cudaFuncAttributeMaxDynamicSharedMemorySize,
                             (int)GEMV_SMEM);
        smem_set = 1;
    }

    proj_gemv<<<260, GEMV_THREADS, GEMV_SMEM>>>(x, Wk, bk, Wv, bv, Wq, bq);
    attn_kernel<<<dim3(NSPLIT, HEADS, BATCH), 256>>>(kc, vc, kout, vout);
    out_gemv<<<128, GEMV_THREADS, GEMV_SMEM>>>(Wo, bo, out);
}